// round 2
// baseline (speedup 1.0000x reference)
#include <cuda_runtime.h>
#include <math.h>

#define BATCH   16
#define NLOC    7581            // 361 + 1444 + 5776 locations over 3 maps
#define NANCH   22743           // NLOC * 3
#define NKEY    1819440         // NANCH * 80 = 240 * NLOC
#define TOPK    4096
#define CAP     8192
#define MAXDET  100

#define NEG_INF __int_as_float(0xff800000)

// ---------------- static device scratch (no allocations allowed) ----------------
__device__ unsigned int       g_keys[(size_t)BATCH * NKEY];   // 116 MB
__device__ float4             g_boxes[BATCH * NANCH];
__device__ float              g_objs[BATCH * 3 * NLOC];
__device__ unsigned int       g_histA[BATCH * 4096];
__device__ unsigned int       g_histB[BATCH * 4096];
__device__ unsigned int       g_histC[BATCH * 256];
__device__ int                g_bin1[BATCH], g_krem1[BATCH];
__device__ int                g_bin2[BATCH], g_krem2[BATCH];
__device__ int                g_bin3[BATCH];
__device__ int                g_cnt[BATCH];
__device__ unsigned long long g_cand[BATCH * CAP];
__device__ float4             g_cbox[BATCH * TOPK];
__device__ float              g_cscore[BATCH * TOPK];
__device__ int                g_clabel[BATCH * TOPK];

// ---------------- per-map constants ----------------
__constant__ int   c_lb[3]  = {0, 361, 1805};      // loc base per map
__constant__ int   c_HW[3]  = {361, 1444, 5776};
__constant__ int   c_W[3]   = {19, 38, 76};
__constant__ int   c_nb[3]  = {0, 1083, 5415};     // anchor base per map
__constant__ float c_str[3] = {32.f, 16.f, 8.f};
// half widths/heights of base anchors, [map][anchor]
__constant__ float c_bw2[9] = {58.f, 78.f, 186.5f,  15.f, 31.f, 29.5f,  5.f, 8.f, 16.5f};
__constant__ float c_bh2[9] = {45.f, 99.f, 163.f,   30.5f, 22.5f, 59.5f, 6.5f, 15.f, 11.5f};

__device__ __forceinline__ float sigm(float x) { return 1.f / (1.f + expf(-x)); }

// ---------------- zero scratch (runs first every graph replay) ----------------
__global__ void zero_kernel() {
    int t = blockIdx.x * blockDim.x + threadIdx.x;
    if (t < BATCH * 4096) { g_histA[t] = 0u; g_histB[t] = 0u; }
    if (t < BATCH * 256)  g_histC[t] = 0u;
    if (t < BATCH)        g_cnt[t] = 0;
}

// ---------------- decode boxes + objectness ----------------
__global__ void decode_kernel(const float* __restrict__ m0,
                              const float* __restrict__ m1,
                              const float* __restrict__ m2) {
    int t = blockIdx.x * blockDim.x + threadIdx.x;
    if (t >= BATCH * 3 * NLOC) return;
    int b = t / (3 * NLOC);
    int r = t - b * 3 * NLOC;
    int a = r / NLOC;
    int locg = r - a * NLOC;
    int m = (locg < 361) ? 0 : ((locg < 1805) ? 1 : 2);
    const float* mp = (m == 0) ? m0 : ((m == 1) ? m1 : m2);
    int HW = c_HW[m];
    int locm = locg - c_lb[m];
    int W = c_W[m];
    float s = c_str[m];
    const float* base = mp + ((size_t)b * 255 + a * 85) * HW + locm;
    float tx = base[0];
    float ty = base[(size_t)HW];
    float tw = base[(size_t)2 * HW];
    float th = base[(size_t)3 * HW];
    float to = base[(size_t)4 * HW];
    float sx = sigm(tx), sy = sigm(ty);
    int h = locm / W, w = locm - h * W;
    float cx = (float)w * s + 0.5f * s + (sx - 0.5f) * s;
    float cy = (float)h * s + 0.5f * s + (sy - 0.5f) * s;
    float wx = c_bw2[m * 3 + a] * expf(tw);
    float wy = c_bh2[m * 3 + a] * expf(th);
    int n = c_nb[m] + locm * 3 + a;
    g_boxes[b * NANCH + n] = make_float4(cx - wx, cy - wy, cx + wx, cy + wy);
    g_objs[(b * 3 + a) * NLOC + locg] = sigm(to);
}

// ---------------- scores -> monotone keys + level-A histogram (top 12 bits) ----------------
// Key storage layout within an image: j = (a*80 + c)*NLOC + locg  (coalesced over locg)
__global__ void score_kernel(const float* __restrict__ m0,
                             const float* __restrict__ m1,
                             const float* __restrict__ m2) {
    __shared__ unsigned int sh[4096];
    int tid = threadIdx.x;
    for (int i = tid; i < 4096; i += blockDim.x) sh[i] = 0u;
    __syncthreads();
    int b = blockIdx.y;
    int base = blockIdx.x * (blockDim.x * 8);
    unsigned int* kp = g_keys + (size_t)b * NKEY;
#pragma unroll
    for (int e = 0; e < 8; e++) {
        int j = base + e * blockDim.x + tid;
        if (j < NKEY) {
            int ac = j / NLOC;
            int locg = j - ac * NLOC;
            int a = ac / 80;
            int c = ac - a * 80;
            int m = (locg < 361) ? 0 : ((locg < 1805) ? 1 : 2);
            const float* mp = (m == 0) ? m0 : ((m == 1) ? m1 : m2);
            int HW = c_HW[m];
            int locm = locg - c_lb[m];
            float cls = mp[((size_t)b * 255 + (a * 85 + 5 + c)) * HW + locm];
            float obj = g_objs[(b * 3 + a) * NLOC + locg];
            float cs = sigm(cls);
            float sc = cs * obj;
            unsigned int key = (obj >= 0.005f && cs > 0.05f)
                                   ? (__float_as_uint(sc) | 0x80000000u) : 0u;
            kp[j] = key;
            atomicAdd(&sh[key >> 20], 1u);
        }
    }
    __syncthreads();
    for (int i = tid; i < 4096; i += blockDim.x) {
        unsigned int v = sh[i];
        if (v) atomicAdd(&g_histA[b * 4096 + i], v);
    }
}

// ---------------- radix-select scan stages ----------------
__global__ void scan_kernel(int stage) {
    int b = threadIdx.x;
    if (b >= BATCH) return;
    if (stage == 0) {
        const unsigned int* h = g_histA + b * 4096;
        int K = TOPK, cum = 0;
        for (int i = 4095; i >= 0; --i) {
            int c = (int)h[i];
            if (cum + c >= K) { g_bin1[b] = i; g_krem1[b] = K - cum; return; }
            cum += c;
        }
        g_bin1[b] = 0; g_krem1[b] = 1;
    } else if (stage == 1) {
        const unsigned int* h = g_histB + b * 4096;
        int K = g_krem1[b], cum = 0;
        for (int i = 4095; i >= 0; --i) {
            int c = (int)h[i];
            if (cum + c >= K) { g_bin2[b] = i; g_krem2[b] = K - cum; return; }
            cum += c;
        }
        g_bin2[b] = 0; g_krem2[b] = 1;
    } else {
        const unsigned int* h = g_histC + b * 256;
        int K = g_krem2[b], cum = 0;
        for (int i = 255; i >= 0; --i) {
            int c = (int)h[i];
            if (cum + c >= K) { g_bin3[b] = i; return; }
            cum += c;
        }
        g_bin3[b] = 0;
    }
}

// ---------------- level-B histogram (middle 12 bits within bin1) ----------------
__global__ void passB_kernel() {
    __shared__ unsigned int sh[4096];
    int tid = threadIdx.x;
    for (int i = tid; i < 4096; i += blockDim.x) sh[i] = 0u;
    __syncthreads();
    int b = blockIdx.y;
    unsigned int bin1 = (unsigned int)g_bin1[b];
    int base = blockIdx.x * (blockDim.x * 8);
    const unsigned int* kp = g_keys + (size_t)b * NKEY;
#pragma unroll
    for (int e = 0; e < 8; e++) {
        int j = base + e * blockDim.x + tid;
        if (j < NKEY) {
            unsigned int key = kp[j];
            if ((key >> 20) == bin1) atomicAdd(&sh[(key >> 8) & 0xFFFu], 1u);
        }
    }
    __syncthreads();
    for (int i = tid; i < 4096; i += blockDim.x) {
        unsigned int v = sh[i];
        if (v) atomicAdd(&g_histB[b * 4096 + i], v);
    }
}

// ---------------- level-C histogram (low 8 bits within prefix24) ----------------
__global__ void passC_kernel() {
    __shared__ unsigned int sh[256];
    int tid = threadIdx.x;
    for (int i = tid; i < 256; i += blockDim.x) sh[i] = 0u;
    __syncthreads();
    int b = blockIdx.y;
    unsigned int pre = ((unsigned int)g_bin1[b] << 12) | (unsigned int)g_bin2[b];
    int base = blockIdx.x * (blockDim.x * 8);
    const unsigned int* kp = g_keys + (size_t)b * NKEY;
#pragma unroll
    for (int e = 0; e < 8; e++) {
        int j = base + e * blockDim.x + tid;
        if (j < NKEY) {
            unsigned int key = kp[j];
            if ((key >> 8) == pre) atomicAdd(&sh[key & 0xFFu], 1u);
        }
    }
    __syncthreads();
    for (int i = tid; i < 256; i += blockDim.x) {
        unsigned int v = sh[i];
        if (v) atomicAdd(&g_histC[b * 256 + i], v);
    }
}

// ---------------- compact all keys >= threshold ----------------
__global__ void compact_kernel() {
    int tid = threadIdx.x;
    int b = blockIdx.y;
    unsigned int T = ((unsigned int)g_bin1[b] << 20) |
                     ((unsigned int)g_bin2[b] << 8)  |
                     (unsigned int)g_bin3[b];
    int base = blockIdx.x * (blockDim.x * 8);
    const unsigned int* kp = g_keys + (size_t)b * NKEY;
#pragma unroll
    for (int e = 0; e < 8; e++) {
        int j = base + e * blockDim.x + tid;
        if (j >= NKEY) continue;
        unsigned int key = kp[j];
        if (key >= T) {
            int pos = atomicAdd(&g_cnt[b], 1);
            if (pos < CAP) {
                int ac = j / NLOC;
                int locg = j - ac * NLOC;
                int a = ac / 80;
                int c = ac - a * 80;
                int m = (locg < 361) ? 0 : ((locg < 1805) ? 1 : 2);
                int n = c_nb[m] + (locg - c_lb[m]) * 3 + a;
                unsigned int idx = (unsigned int)(n * 80 + c);
                g_cand[b * CAP + pos] =
                    (((unsigned long long)(~key)) << 32) | (unsigned long long)idx;
            }
        }
    }
}

// ---------------- per-image bitonic sort of candidates + gather ----------------
__global__ __launch_bounds__(1024) void sort_kernel() {
    extern __shared__ unsigned long long sd[];
    int b = blockIdx.x;
    int tid = threadIdx.x;
    int cnt = g_cnt[b];
    if (cnt > CAP) cnt = CAP;
    for (int i = tid; i < CAP; i += 1024)
        sd[i] = (i < cnt) ? g_cand[b * CAP + i] : 0xFFFFFFFFFFFFFFFFull;
    __syncthreads();
    for (int k = 2; k <= CAP; k <<= 1) {
        for (int j = k >> 1; j > 0; j >>= 1) {
            for (int i = tid; i < CAP; i += 1024) {
                int ix = i ^ j;
                if (ix > i) {
                    unsigned long long A = sd[i], Bv = sd[ix];
                    bool up = ((i & k) == 0);
                    if ((A > Bv) == up) { sd[i] = Bv; sd[ix] = A; }
                }
            }
            __syncthreads();
        }
    }
    // sorted ascending on (~key, idx) == score desc, index asc  (exact top_k order)
    for (int i = tid; i < TOPK; i += 1024) {
        unsigned long long e = sd[i];
        unsigned int key = ~(unsigned int)(e >> 32);
        unsigned int idx = (unsigned int)(e & 0xFFFFFFFFu);
        float sc;
        if (key == 0u) { sc = NEG_INF; idx = 0u; }
        else           { sc = __uint_as_float(key & 0x7FFFFFFFu); }
        int n = idx / 80;
        int lbl = (int)idx - n * 80;
        g_cbox[b * TOPK + i] = g_boxes[b * NANCH + n];
        g_cscore[b * TOPK + i] = sc;
        g_clabel[b * TOPK + i] = lbl;
    }
}

// ---------------- greedy NMS (one block per image) ----------------
__global__ __launch_bounds__(1024) void nms_kernel(float* __restrict__ out, int out_size) {
    extern __shared__ char smraw[];
    float4* sbox = (float4*)smraw;            // TOPK * 16 B
    float*  ss   = (float*)(sbox + TOPK);     // TOPK * 4 B (alive scores)
    float*  soff = ss + TOPK;                 // TOPK * 4 B (class offsets)
    int*    slbl = (int*)(soff + TOPK);       // TOPK * 4 B
    __shared__ float wred[32];
    __shared__ float smaxc;
    __shared__ int sj, skeep, sfront;

    int b = blockIdx.x, tid = threadIdx.x;
    float lmax = NEG_INF;
    for (int i = tid; i < TOPK; i += 1024) {
        float4 bx = g_cbox[b * TOPK + i];
        float sc = g_cscore[b * TOPK + i];
        sbox[i] = bx; ss[i] = sc; slbl[i] = g_clabel[b * TOPK + i];
        float rm = (sc == NEG_INF) ? 0.f
                                   : fmaxf(fmaxf(bx.x, bx.y), fmaxf(bx.z, bx.w));
        lmax = fmaxf(lmax, rm);
    }
    // block max-reduce
    for (int o = 16; o > 0; o >>= 1) lmax = fmaxf(lmax, __shfl_xor_sync(0xffffffffu, lmax, o));
    if ((tid & 31) == 0) wred[tid >> 5] = lmax;
    __syncthreads();
    if (tid < 32) {
        float v = (tid < 32) ? wred[tid] : NEG_INF;
        for (int o = 16; o > 0; o >>= 1) v = fmaxf(v, __shfl_xor_sync(0xffffffffu, v, o));
        if (tid == 0) { smaxc = v; sfront = 0; }
    }
    __syncthreads();
    float ob = smaxc + 1.0f;
    for (int i = tid; i < TOPK; i += 1024) soff[i] = (float)slbl[i] * ob;
    __syncthreads();

    for (int it = 0; it < MAXDET; ++it) {
        if (tid == 0) {
            int f = sfront;
            while (f < TOPK && ss[f] == NEG_INF) ++f;
            sfront = f;
            int keep = (f < TOPK && ss[f] > 0.f) ? 1 : 0;
            int j = (f < TOPK) ? f : 0;
            sj = j; skeep = keep;
            float* o = out + (size_t)(b * MAXDET + it) * 5;
            if (keep) {
                float4 bx = sbox[j];
                o[0] = bx.x; o[1] = bx.y; o[2] = bx.z; o[3] = bx.w; o[4] = ss[j];
            } else {
                o[0] = 0.f; o[1] = 0.f; o[2] = 0.f; o[3] = 0.f; o[4] = 0.f;
            }
            if (out_size > BATCH * MAXDET * 5)
                out[BATCH * MAXDET * 5 + b * MAXDET + it] = keep ? (float)slbl[j] : -1.0f;
        }
        __syncthreads();
        if (skeep) {
            int j = sj;
            float oj = soff[j];
            float4 bj = sbox[j];
            float jx0 = bj.x + oj, jy0 = bj.y + oj, jx1 = bj.z + oj, jy1 = bj.w + oj;
            float a1 = (jx1 - jx0) * (jy1 - jy0);
            for (int t = tid; t < TOPK; t += 1024) {
                float sct = ss[t];
                if (sct != NEG_INF) {
                    float ot = soff[t];
                    float4 bt = sbox[t];
                    float tx0 = bt.x + ot, ty0 = bt.y + ot, tx1 = bt.z + ot, ty1 = bt.w + ot;
                    float tlx = fmaxf(jx0, tx0), tly = fmaxf(jy0, ty0);
                    float brx = fminf(jx1, tx1), bry = fminf(jy1, ty1);
                    float iw = fmaxf(brx - tlx, 0.f), ih = fmaxf(bry - tly, 0.f);
                    float inter = iw * ih;
                    float a2 = (tx1 - tx0) * (ty1 - ty0);
                    float iou = inter / (a1 + a2 - inter + 1e-12f);
                    if (iou > 0.45f) ss[t] = NEG_INF;
                }
            }
        }
        __syncthreads();
    }
}

// ---------------- launcher ----------------
extern "C" void kernel_launch(void* const* d_in, const int* in_sizes, int n_in,
                              void* d_out, int out_size) {
    const float* m0 = (const float*)d_in[0];
    const float* m1 = (const float*)d_in[1];
    const float* m2 = (const float*)d_in[2];
    float* out = (float*)d_out;

    cudaFuncSetAttribute(sort_kernel, cudaFuncAttributeMaxDynamicSharedMemorySize, CAP * 8);
    cudaFuncSetAttribute(nms_kernel,  cudaFuncAttributeMaxDynamicSharedMemorySize, TOPK * 28);

    zero_kernel<<<(BATCH * 4096 + 255) / 256, 256>>>();
    decode_kernel<<<(BATCH * 3 * NLOC + 255) / 256, 256>>>(m0, m1, m2);

    dim3 pg((NKEY + 2047) / 2048, BATCH);
    score_kernel<<<pg, 256>>>(m0, m1, m2);
    scan_kernel<<<1, BATCH>>>(0);
    passB_kernel<<<pg, 256>>>();
    scan_kernel<<<1, BATCH>>>(1);
    passC_kernel<<<pg, 256>>>();
    scan_kernel<<<1, BATCH>>>(2);
    compact_kernel<<<pg, 256>>>();
    sort_kernel<<<BATCH, 1024, CAP * 8>>>();
    nms_kernel<<<BATCH, 1024, TOPK * 28>>>(out, out_size);
}

// round 3
// speedup vs baseline: 1.0002x; 1.0002x over previous
#include <cuda_runtime.h>
#include <math.h>

#define BATCH   16
#define NLOC    7581            // 361 + 1444 + 5776 locations over 3 maps
#define NANCH   22743           // NLOC * 3
#define NKEY    1819440         // NANCH * 80 = 240 * NLOC
#define TOPK    4096
#define CAP     8192
#define MAXDET  100

#define NEG_INF __int_as_float(0xff800000)

// ---------------- static device scratch (no allocations allowed) ----------------
__device__ unsigned int       g_keys[(size_t)BATCH * NKEY];   // 116 MB
__device__ float4             g_boxes[BATCH * NANCH];
__device__ float              g_objs[BATCH * 3 * NLOC];
__device__ unsigned int       g_histA[BATCH * 4096];
__device__ unsigned int       g_histB[BATCH * 4096];
__device__ unsigned int       g_histC[BATCH * 256];
__device__ int                g_bin1[BATCH], g_krem1[BATCH];
__device__ int                g_bin2[BATCH], g_krem2[BATCH];
__device__ int                g_bin3[BATCH];
__device__ int                g_cnt[BATCH];
__device__ unsigned long long g_cand[BATCH * CAP];
__device__ float4             g_cbox[BATCH * TOPK];
__device__ float              g_cscore[BATCH * TOPK];
__device__ int                g_clabel[BATCH * TOPK];

// ---------------- per-map constants ----------------
__constant__ int   c_lb[3]  = {0, 361, 1805};      // loc base per map
__constant__ int   c_HW[3]  = {361, 1444, 5776};
__constant__ int   c_W[3]   = {19, 38, 76};
__constant__ int   c_nb[3]  = {0, 1083, 5415};     // anchor base per map
__constant__ float c_str[3] = {32.f, 16.f, 8.f};
// half widths/heights of base anchors, [map][anchor]
__constant__ float c_bw2[9] = {58.f, 78.f, 186.5f,  15.f, 31.f, 29.5f,  5.f, 8.f, 16.5f};
__constant__ float c_bh2[9] = {45.f, 99.f, 163.f,   30.5f, 22.5f, 59.5f, 6.5f, 15.f, 11.5f};

__device__ __forceinline__ float sigm(float x) { return 1.f / (1.f + expf(-x)); }

// ---------------- zero scratch (runs first every graph replay) ----------------
__global__ void zero_kernel() {
    int t = blockIdx.x * blockDim.x + threadIdx.x;
    if (t < BATCH * 4096) { g_histA[t] = 0u; g_histB[t] = 0u; }
    if (t < BATCH * 256)  g_histC[t] = 0u;
    if (t < BATCH)        g_cnt[t] = 0;
}

// ---------------- decode boxes + objectness ----------------
__global__ void decode_kernel(const float* __restrict__ m0,
                              const float* __restrict__ m1,
                              const float* __restrict__ m2) {
    int t = blockIdx.x * blockDim.x + threadIdx.x;
    if (t >= BATCH * 3 * NLOC) return;
    int b = t / (3 * NLOC);
    int r = t - b * 3 * NLOC;
    int a = r / NLOC;
    int locg = r - a * NLOC;
    int m = (locg < 361) ? 0 : ((locg < 1805) ? 1 : 2);
    const float* mp = (m == 0) ? m0 : ((m == 1) ? m1 : m2);
    int HW = c_HW[m];
    int locm = locg - c_lb[m];
    int W = c_W[m];
    float s = c_str[m];
    const float* base = mp + ((size_t)b * 255 + a * 85) * HW + locm;
    float tx = base[0];
    float ty = base[(size_t)HW];
    float tw = base[(size_t)2 * HW];
    float th = base[(size_t)3 * HW];
    float to = base[(size_t)4 * HW];
    float sx = sigm(tx), sy = sigm(ty);
    int h = locm / W, w = locm - h * W;
    float cx = (float)w * s + 0.5f * s + (sx - 0.5f) * s;
    float cy = (float)h * s + 0.5f * s + (sy - 0.5f) * s;
    float wx = c_bw2[m * 3 + a] * expf(tw);
    float wy = c_bh2[m * 3 + a] * expf(th);
    int n = c_nb[m] + locm * 3 + a;
    g_boxes[b * NANCH + n] = make_float4(cx - wx, cy - wy, cx + wx, cy + wy);
    g_objs[(b * 3 + a) * NLOC + locg] = sigm(to);
}

// ---------------- scores -> monotone keys + level-A histogram (top 12 bits) ----------------
// Key storage layout within an image: j = (a*80 + c)*NLOC + locg  (coalesced over locg)
__global__ void score_kernel(const float* __restrict__ m0,
                             const float* __restrict__ m1,
                             const float* __restrict__ m2) {
    __shared__ unsigned int sh[4096];
    int tid = threadIdx.x;
    for (int i = tid; i < 4096; i += blockDim.x) sh[i] = 0u;
    __syncthreads();
    int b = blockIdx.y;
    int base = blockIdx.x * (blockDim.x * 8);
    unsigned int* kp = g_keys + (size_t)b * NKEY;
#pragma unroll
    for (int e = 0; e < 8; e++) {
        int j = base + e * blockDim.x + tid;
        if (j < NKEY) {
            int ac = j / NLOC;
            int locg = j - ac * NLOC;
            int a = ac / 80;
            int c = ac - a * 80;
            int m = (locg < 361) ? 0 : ((locg < 1805) ? 1 : 2);
            const float* mp = (m == 0) ? m0 : ((m == 1) ? m1 : m2);
            int HW = c_HW[m];
            int locm = locg - c_lb[m];
            float cls = mp[((size_t)b * 255 + (a * 85 + 5 + c)) * HW + locm];
            float obj = g_objs[(b * 3 + a) * NLOC + locg];
            float cs = sigm(cls);
            float sc = cs * obj;
            unsigned int key = (obj >= 0.005f && cs > 0.05f)
                                   ? (__float_as_uint(sc) | 0x80000000u) : 0u;
            kp[j] = key;
            atomicAdd(&sh[key >> 20], 1u);
        }
    }
    __syncthreads();
    for (int i = tid; i < 4096; i += blockDim.x) {
        unsigned int v = sh[i];
        if (v) atomicAdd(&g_histA[b * 4096 + i], v);
    }
}

// ---------------- radix-select scan stages ----------------
__global__ void scan_kernel(int stage) {
    int b = threadIdx.x;
    if (b >= BATCH) return;
    if (stage == 0) {
        const unsigned int* h = g_histA + b * 4096;
        int K = TOPK, cum = 0;
        for (int i = 4095; i >= 0; --i) {
            int c = (int)h[i];
            if (cum + c >= K) { g_bin1[b] = i; g_krem1[b] = K - cum; return; }
            cum += c;
        }
        g_bin1[b] = 0; g_krem1[b] = 1;
    } else if (stage == 1) {
        const unsigned int* h = g_histB + b * 4096;
        int K = g_krem1[b], cum = 0;
        for (int i = 4095; i >= 0; --i) {
            int c = (int)h[i];
            if (cum + c >= K) { g_bin2[b] = i; g_krem2[b] = K - cum; return; }
            cum += c;
        }
        g_bin2[b] = 0; g_krem2[b] = 1;
    } else {
        const unsigned int* h = g_histC + b * 256;
        int K = g_krem2[b], cum = 0;
        for (int i = 255; i >= 0; --i) {
            int c = (int)h[i];
            if (cum + c >= K) { g_bin3[b] = i; return; }
            cum += c;
        }
        g_bin3[b] = 0;
    }
}

// ---------------- level-B histogram (middle 12 bits within bin1) ----------------
__global__ void passB_kernel() {
    __shared__ unsigned int sh[4096];
    int tid = threadIdx.x;
    for (int i = tid; i < 4096; i += blockDim.x) sh[i] = 0u;
    __syncthreads();
    int b = blockIdx.y;
    unsigned int bin1 = (unsigned int)g_bin1[b];
    int base = blockIdx.x * (blockDim.x * 8);
    const unsigned int* kp = g_keys + (size_t)b * NKEY;
#pragma unroll
    for (int e = 0; e < 8; e++) {
        int j = base + e * blockDim.x + tid;
        if (j < NKEY) {
            unsigned int key = kp[j];
            if ((key >> 20) == bin1) atomicAdd(&sh[(key >> 8) & 0xFFFu], 1u);
        }
    }
    __syncthreads();
    for (int i = tid; i < 4096; i += blockDim.x) {
        unsigned int v = sh[i];
        if (v) atomicAdd(&g_histB[b * 4096 + i], v);
    }
}

// ---------------- level-C histogram (low 8 bits within prefix24) ----------------
__global__ void passC_kernel() {
    __shared__ unsigned int sh[256];
    int tid = threadIdx.x;
    for (int i = tid; i < 256; i += blockDim.x) sh[i] = 0u;
    __syncthreads();
    int b = blockIdx.y;
    unsigned int pre = ((unsigned int)g_bin1[b] << 12) | (unsigned int)g_bin2[b];
    int base = blockIdx.x * (blockDim.x * 8);
    const unsigned int* kp = g_keys + (size_t)b * NKEY;
#pragma unroll
    for (int e = 0; e < 8; e++) {
        int j = base + e * blockDim.x + tid;
        if (j < NKEY) {
            unsigned int key = kp[j];
            if ((key >> 8) == pre) atomicAdd(&sh[key & 0xFFu], 1u);
        }
    }
    __syncthreads();
    for (int i = tid; i < 256; i += blockDim.x) {
        unsigned int v = sh[i];
        if (v) atomicAdd(&g_histC[b * 256 + i], v);
    }
}

// ---------------- compact all keys >= threshold ----------------
__global__ void compact_kernel() {
    int tid = threadIdx.x;
    int b = blockIdx.y;
    unsigned int T = ((unsigned int)g_bin1[b] << 20) |
                     ((unsigned int)g_bin2[b] << 8)  |
                     (unsigned int)g_bin3[b];
    int base = blockIdx.x * (blockDim.x * 8);
    const unsigned int* kp = g_keys + (size_t)b * NKEY;
#pragma unroll
    for (int e = 0; e < 8; e++) {
        int j = base + e * blockDim.x + tid;
        if (j >= NKEY) continue;
        unsigned int key = kp[j];
        if (key >= T) {
            int pos = atomicAdd(&g_cnt[b], 1);
            if (pos < CAP) {
                int ac = j / NLOC;
                int locg = j - ac * NLOC;
                int a = ac / 80;
                int c = ac - a * 80;
                int m = (locg < 361) ? 0 : ((locg < 1805) ? 1 : 2);
                int n = c_nb[m] + (locg - c_lb[m]) * 3 + a;
                unsigned int idx = (unsigned int)(n * 80 + c);
                g_cand[b * CAP + pos] =
                    (((unsigned long long)(~key)) << 32) | (unsigned long long)idx;
            }
        }
    }
}

// ---------------- per-image bitonic sort of candidates + gather ----------------
__global__ __launch_bounds__(1024) void sort_kernel() {
    extern __shared__ unsigned long long sd[];
    int b = blockIdx.x;
    int tid = threadIdx.x;
    int cnt = g_cnt[b];
    if (cnt > CAP) cnt = CAP;
    for (int i = tid; i < CAP; i += 1024)
        sd[i] = (i < cnt) ? g_cand[b * CAP + i] : 0xFFFFFFFFFFFFFFFFull;
    __syncthreads();
    for (int k = 2; k <= CAP; k <<= 1) {
        for (int j = k >> 1; j > 0; j >>= 1) {
            for (int i = tid; i < CAP; i += 1024) {
                int ix = i ^ j;
                if (ix > i) {
                    unsigned long long A = sd[i], Bv = sd[ix];
                    bool up = ((i & k) == 0);
                    if ((A > Bv) == up) { sd[i] = Bv; sd[ix] = A; }
                }
            }
            __syncthreads();
        }
    }
    // sorted ascending on (~key, idx) == score desc, index asc  (exact top_k order)
    for (int i = tid; i < TOPK; i += 1024) {
        unsigned long long e = sd[i];
        unsigned int key = ~(unsigned int)(e >> 32);
        unsigned int idx = (unsigned int)(e & 0xFFFFFFFFu);
        float sc;
        if (key == 0u) { sc = NEG_INF; idx = 0u; }
        else           { sc = __uint_as_float(key & 0x7FFFFFFFu); }
        int n = idx / 80;
        int lbl = (int)idx - n * 80;
        g_cbox[b * TOPK + i] = g_boxes[b * NANCH + n];
        g_cscore[b * TOPK + i] = sc;
        g_clabel[b * TOPK + i] = lbl;
    }
}

// ---------------- greedy NMS (one block per image) ----------------
__global__ __launch_bounds__(1024) void nms_kernel(float* __restrict__ out, int out_size) {
    extern __shared__ char smraw[];
    float4* sbox = (float4*)smraw;            // TOPK * 16 B
    float*  ss   = (float*)(sbox + TOPK);     // TOPK * 4 B (alive scores)
    float*  soff = ss + TOPK;                 // TOPK * 4 B (class offsets)
    int*    slbl = (int*)(soff + TOPK);       // TOPK * 4 B
    __shared__ float wred[32];
    __shared__ float smaxc;
    __shared__ int sj, skeep, sfront;

    int b = blockIdx.x, tid = threadIdx.x;
    float lmax = NEG_INF;
    for (int i = tid; i < TOPK; i += 1024) {
        float4 bx = g_cbox[b * TOPK + i];
        float sc = g_cscore[b * TOPK + i];
        sbox[i] = bx; ss[i] = sc; slbl[i] = g_clabel[b * TOPK + i];
        float rm = (sc == NEG_INF) ? 0.f
                                   : fmaxf(fmaxf(bx.x, bx.y), fmaxf(bx.z, bx.w));
        lmax = fmaxf(lmax, rm);
    }
    // block max-reduce
    for (int o = 16; o > 0; o >>= 1) lmax = fmaxf(lmax, __shfl_xor_sync(0xffffffffu, lmax, o));
    if ((tid & 31) == 0) wred[tid >> 5] = lmax;
    __syncthreads();
    if (tid < 32) {
        float v = (tid < 32) ? wred[tid] : NEG_INF;
        for (int o = 16; o > 0; o >>= 1) v = fmaxf(v, __shfl_xor_sync(0xffffffffu, v, o));
        if (tid == 0) { smaxc = v; sfront = 0; }
    }
    __syncthreads();
    float ob = smaxc + 1.0f;
    for (int i = tid; i < TOPK; i += 1024) soff[i] = (float)slbl[i] * ob;
    __syncthreads();

    for (int it = 0; it < MAXDET; ++it) {
        if (tid == 0) {
            int f = sfront;
            while (f < TOPK && ss[f] == NEG_INF) ++f;
            sfront = f;
            int keep = (f < TOPK && ss[f] > 0.f) ? 1 : 0;
            int j = (f < TOPK) ? f : 0;
            sj = j; skeep = keep;
            float* o = out + (size_t)(b * MAXDET + it) * 5;
            if (keep) {
                float4 bx = sbox[j];
                o[0] = bx.x; o[1] = bx.y; o[2] = bx.z; o[3] = bx.w; o[4] = ss[j];
            } else {
                o[0] = 0.f; o[1] = 0.f; o[2] = 0.f; o[3] = 0.f; o[4] = 0.f;
            }
            if (out_size > BATCH * MAXDET * 5)
                out[BATCH * MAXDET * 5 + b * MAXDET + it] = keep ? (float)slbl[j] : -1.0f;
        }
        __syncthreads();
        if (skeep) {
            int j = sj;
            float oj = soff[j];
            float4 bj = sbox[j];
            float jx0 = bj.x + oj, jy0 = bj.y + oj, jx1 = bj.z + oj, jy1 = bj.w + oj;
            float a1 = (jx1 - jx0) * (jy1 - jy0);
            for (int t = tid; t < TOPK; t += 1024) {
                float sct = ss[t];
                if (sct != NEG_INF) {
                    float ot = soff[t];
                    float4 bt = sbox[t];
                    float tx0 = bt.x + ot, ty0 = bt.y + ot, tx1 = bt.z + ot, ty1 = bt.w + ot;
                    float tlx = fmaxf(jx0, tx0), tly = fmaxf(jy0, ty0);
                    float brx = fminf(jx1, tx1), bry = fminf(jy1, ty1);
                    float iw = fmaxf(brx - tlx, 0.f), ih = fmaxf(bry - tly, 0.f);
                    float inter = iw * ih;
                    float a2 = (tx1 - tx0) * (ty1 - ty0);
                    float iou = inter / (a1 + a2 - inter + 1e-12f);
                    if (iou > 0.45f) ss[t] = NEG_INF;
                }
            }
        }
        __syncthreads();
    }
}

// ---------------- launcher ----------------
extern "C" void kernel_launch(void* const* d_in, const int* in_sizes, int n_in,
                              void* d_out, int out_size) {
    const float* m0 = (const float*)d_in[0];
    const float* m1 = (const float*)d_in[1];
    const float* m2 = (const float*)d_in[2];
    float* out = (float*)d_out;

    cudaFuncSetAttribute(sort_kernel, cudaFuncAttributeMaxDynamicSharedMemorySize, CAP * 8);
    cudaFuncSetAttribute(nms_kernel,  cudaFuncAttributeMaxDynamicSharedMemorySize, TOPK * 28);

    zero_kernel<<<(BATCH * 4096 + 255) / 256, 256>>>();
    decode_kernel<<<(BATCH * 3 * NLOC + 255) / 256, 256>>>(m0, m1, m2);

    dim3 pg((NKEY + 2047) / 2048, BATCH);
    score_kernel<<<pg, 256>>>(m0, m1, m2);
    scan_kernel<<<1, BATCH>>>(0);
    passB_kernel<<<pg, 256>>>();
    scan_kernel<<<1, BATCH>>>(1);
    passC_kernel<<<pg, 256>>>();
    scan_kernel<<<1, BATCH>>>(2);
    compact_kernel<<<pg, 256>>>();
    sort_kernel<<<BATCH, 1024, CAP * 8>>>();
    nms_kernel<<<BATCH, 1024, TOPK * 28>>>(out, out_size);
}

// round 4
// speedup vs baseline: 1.5420x; 1.5417x over previous
#include <cuda_runtime.h>
#include <math.h>

#define BATCH   16
#define NLOC    7581
#define NANCH   22743
#define TOPK    4096
#define CAP2    131072          // per-image candidate cap (global)
#define CAPS    8192            // in-block sort size
#define MAXDET  100
#define NBINS   8192

#define NEG_INF __int_as_float(0xff800000)

__device__ float              g_objs[BATCH * 3 * NLOC];
__device__ float              g_thr [BATCH * 3 * NLOC];
__device__ unsigned int       g_hist[BATCH * NBINS];
__device__ unsigned int       g_lbkey[BATCH];
__device__ int                g_cnt[BATCH];
__device__ unsigned long long g_cand[(size_t)BATCH * CAP2];

__constant__ int   c_lb[3]  = {0, 361, 1805};
__constant__ int   c_HW[3]  = {361, 1444, 5776};
__constant__ int   c_W[3]   = {19, 38, 76};
__constant__ int   c_nb[3]  = {0, 1083, 5415};
__constant__ float c_str[3] = {32.f, 16.f, 8.f};
__constant__ float c_bw2[9] = {58.f, 78.f, 186.5f,  15.f, 31.f, 29.5f,  5.f, 8.f, 16.5f};
__constant__ float c_bh2[9] = {45.f, 99.f, 163.f,   30.5f, 22.5f, 59.5f, 6.5f, 15.f, 11.5f};

__device__ __forceinline__ float sigm(float x) { return 1.f / (1.f + expf(-x)); }

// ---------------- objectness + zero scratch ----------------
__global__ void obj_kernel(const float* __restrict__ m0,
                           const float* __restrict__ m1,
                           const float* __restrict__ m2) {
    int t = blockIdx.x * blockDim.x + threadIdx.x;
    if (t < BATCH * NBINS) g_hist[t] = 0u;
    if (t < BATCH)         g_cnt[t] = 0;
    if (t >= BATCH * 3 * NLOC) return;
    int b = t / (3 * NLOC);
    int r = t - b * 3 * NLOC;
    int a = r / NLOC;
    int locg = r - a * NLOC;
    int m = (locg < 361) ? 0 : ((locg < 1805) ? 1 : 2);
    int locm = locg - c_lb[m];
    const float* mp = (m == 0) ? m0 : ((m == 1) ? m1 : m2);
    float to = mp[((size_t)b * 255 + a * 85 + 4) * (size_t)c_HW[m] + locm];
    g_objs[t] = sigm(to);
}

// ---------------- per-anchor max class logit -> key histogram ----------------
__global__ __launch_bounds__(512) void amax_kernel(const float* __restrict__ m0,
                                                   const float* __restrict__ m1,
                                                   const float* __restrict__ m2) {
    __shared__ unsigned int sh[NBINS];
    int tid = threadIdx.x;
    for (int i = tid; i < NBINS; i += 512) sh[i] = 0u;
    __syncthreads();
    int b = blockIdx.z, a = blockIdx.y;
    int locg = blockIdx.x * 512 + tid;
    if (locg < NLOC) {
        int m = (locg < 361) ? 0 : ((locg < 1805) ? 1 : 2);
        int locm = locg - c_lb[m];
        const float* mp = (m == 0) ? m0 : ((m == 1) ? m1 : m2);
        size_t HW = (size_t)c_HW[m];
        const float* base = mp + ((size_t)b * 255 + a * 85 + 5) * HW + locm;
        float cm = -1e30f;
#pragma unroll 8
        for (int ch = 0; ch < 80; ++ch) cm = fmaxf(cm, base[(size_t)ch * HW]);
        float obj = g_objs[(b * 3 + a) * NLOC + locg];
        float cs = sigm(cm);
        unsigned int key = (obj >= 0.005f && cs > 0.05f)
                               ? (__float_as_uint(cs * obj) | 0x80000000u) : 0u;
        atomicAdd(&sh[key >> 19], 1u);
    }
    __syncthreads();
    for (int i = tid; i < NBINS; i += 512) {
        unsigned int v = sh[i];
        if (v) atomicAdd(&g_hist[b * NBINS + i], v);
    }
}

// ---- parallel top-down bin finder over an 8192-bin smem histogram (1024 thr) ----
__device__ __forceinline__ void find_bin_top(const unsigned int* hist, int K,
                                             int* part, int* wsum,
                                             int* out_bin, int* out_above) {
    int tid = threadIdx.x;
    int s = 0;
#pragma unroll
    for (int k = 0; k < 8; k++) s += (int)hist[tid * 8 + k];
    part[tid] = s;
    int v = s;
    for (int o = 16; o; o >>= 1) v += __shfl_xor_sync(0xffffffffu, v, o);
    if ((tid & 31) == 0) wsum[tid >> 5] = v;
    __syncthreads();
    if (tid == 0) {
        int cum = 0, bin = 0, wi;
        for (wi = 31; wi >= 0; --wi) {
            if (cum + wsum[wi] >= K) break;
            cum += wsum[wi];
        }
        if (wi >= 0) {
            int p;
            for (p = wi * 32 + 31; p > wi * 32; --p) {
                if (cum + part[p] >= K) break;
                cum += part[p];
            }
            int bb;
            for (bb = p * 8 + 7; bb > p * 8; --bb) {
                if (cum + (int)hist[bb] >= K) break;
                cum += (int)hist[bb];
            }
            bin = bb;
        }
        *out_bin = bin; *out_above = cum;
    }
    __syncthreads();
}

// ---------------- LB + per-anchor raw-logit thresholds ----------------
__global__ __launch_bounds__(1024) void thr_kernel() {
    __shared__ unsigned int h[NBINS];
    __shared__ int part[1024];
    __shared__ int wsum[32];
    __shared__ int sbin, sabove;
    int b = blockIdx.x, tid = threadIdx.x;
    for (int i = tid; i < NBINS; i += 1024) h[i] = g_hist[b * NBINS + i];
    __syncthreads();
    find_bin_top(h, TOPK, part, wsum, &sbin, &sabove);
    unsigned int lbkey = ((unsigned int)sbin) << 19;
    if (tid == 0) g_lbkey[b] = lbkey;
    float LB = __uint_as_float(lbkey & 0x7FFFFFFFu);
    for (int r = tid; r < 3 * NLOC; r += 1024) {
        float obj = g_objs[b * 3 * NLOC + r];
        float thr;
        if (obj < 0.005f) thr = 3.0e38f;
        else if (LB <= 0.f) thr = -2.9446f;
        else {
            float ratio = LB / obj;
            if (ratio >= 1.0f) thr = 3.0e38f;
            else thr = fmaxf(logf(ratio / (1.0f - ratio)) - 1e-2f, -2.9446f);
        }
        g_thr[b * 3 * NLOC + r] = thr;
    }
}

// ---------------- candidate generation ----------------
__global__ __launch_bounds__(512) void cand_kernel(const float* __restrict__ m0,
                                                   const float* __restrict__ m1,
                                                   const float* __restrict__ m2) {
    int b = blockIdx.z;
    int ac = blockIdx.y;            // 0..239
    int a = ac / 80, cl = ac - a * 80;
    int tid = threadIdx.x;
    int locg = blockIdx.x * 512 + tid;
    bool emit = false;
    unsigned long long pk = 0ull;
    if (locg < NLOC) {
        int m = (locg < 361) ? 0 : ((locg < 1805) ? 1 : 2);
        int locm = locg - c_lb[m];
        const float* mp = (m == 0) ? m0 : ((m == 1) ? m1 : m2);
        float c = mp[((size_t)b * 255 + a * 85 + 5 + cl) * (size_t)c_HW[m] + locm];
        float thr = g_thr[(b * 3 + a) * NLOC + locg];
        if (c >= thr) {
            float obj = g_objs[(b * 3 + a) * NLOC + locg];
            float cs = sigm(c);
            if (cs > 0.05f && obj >= 0.005f) {
                unsigned int key = __float_as_uint(cs * obj) | 0x80000000u;
                if (key >= g_lbkey[b]) {
                    int nI = c_nb[m] + locm * 3 + a;
                    unsigned int idx = (unsigned int)nI * 80u + (unsigned int)cl;
                    pk = (((unsigned long long)(~key)) << 32) | (unsigned long long)idx;
                    emit = true;
                }
            }
        }
    }
    unsigned int mask = __ballot_sync(0xffffffffu, emit);
    if (mask) {
        int lane = tid & 31;
        int leader = __ffs(mask) - 1;
        int basep = 0;
        if (lane == leader) basep = atomicAdd(&g_cnt[b], __popc(mask));
        basep = __shfl_sync(0xffffffffu, basep, leader);
        if (emit) {
            int pos = basep + __popc(mask & ((1u << lane) - 1u));
            if (pos < CAP2) g_cand[(size_t)b * CAP2 + pos] = pk;
        }
    }
}

// ---------------- select + sort + decode + NMS (one block per image) ----------------
__global__ __launch_bounds__(1024) void finish_kernel(const float* __restrict__ m0,
                                                      const float* __restrict__ m1,
                                                      const float* __restrict__ m2,
                                                      float* __restrict__ out, int out_size) {
    extern __shared__ char smraw[];
    unsigned long long* scand = (unsigned long long*)smraw;          // 64 KB
    char* nb = smraw + 65536;
    float4* sbox = (float4*)nb;                                      // 64 KB
    float*  ss   = (float*)(nb + 65536);                             // 16 KB
    float*  soff = (float*)(nb + 81920);                             // 16 KB
    int*    slbl = (int*)(nb + 98304);                               // 16 KB
    unsigned int* hist = (unsigned int*)nb;                          // pre-sort only
    __shared__ int part[1024];
    __shared__ int wsum[32];
    __shared__ unsigned int salive[128];
    __shared__ float wred[32];
    __shared__ int st2, sgt, st3, sdum, scc;
    __shared__ int sj, skeep, sfrontw;
    __shared__ float smaxc;

    int b = blockIdx.x, tid = threadIdx.x;
    int n = g_cnt[b]; if (n > CAP2) n = CAP2;
    const unsigned long long* cand = g_cand + (size_t)b * CAP2;

    // level-1: top 13 bits of key
    for (int i = tid; i < NBINS; i += 1024) hist[i] = 0u;
    __syncthreads();
    for (int i = tid; i < n; i += 1024) {
        unsigned int key = ~(unsigned int)(cand[i] >> 32);
        atomicAdd(&hist[key >> 19], 1u);
    }
    __syncthreads();
    find_bin_top(hist, TOPK, part, wsum, &st2, &sgt);
    int t2 = st2, gt = sgt;
    __syncthreads();
    // level-2: bits [6,19) within bin t2
    for (int i = tid; i < NBINS; i += 1024) hist[i] = 0u;
    __syncthreads();
    for (int i = tid; i < n; i += 1024) {
        unsigned int key = ~(unsigned int)(cand[i] >> 32);
        if ((int)(key >> 19) == t2) atomicAdd(&hist[(key >> 6) & 0x1FFFu], 1u);
    }
    __syncthreads();
    find_bin_top(hist, TOPK - gt, part, wsum, &st3, &sdum);
    int t3 = st3;
    if (tid == 0) scc = 0;
    __syncthreads();
    // compact refined-threshold survivors into smem
    for (int i = tid; i < n; i += 1024) {
        unsigned long long e = cand[i];
        unsigned int key = ~(unsigned int)(e >> 32);
        int hb = (int)(key >> 19);
        bool keep = (hb > t2) || (hb == t2 && (int)((key >> 6) & 0x1FFFu) >= t3);
        if (keep) {
            int p = atomicAdd(&scc, 1);
            if (p < CAPS) scand[p] = e;
        }
    }
    __syncthreads();
    int c2 = scc; if (c2 > CAPS) c2 = CAPS;
    for (int i = tid; i < CAPS; i += 1024)
        if (i >= c2) scand[i] = 0xFFFFFFFFFFFFFFFFull;
    __syncthreads();
    // bitonic sort ascending on (~key, idx) == (score desc, idx asc)
    for (int k = 2; k <= CAPS; k <<= 1) {
        for (int j = k >> 1; j > 0; j >>= 1) {
            for (int i = tid; i < CAPS; i += 1024) {
                int ix = i ^ j;
                if (ix > i) {
                    unsigned long long A = scand[i], B = scand[ix];
                    bool up = ((i & k) == 0);
                    if ((A > B) == up) { scand[i] = B; scand[ix] = A; }
                }
            }
            __syncthreads();
        }
    }
    // gather top-4096: decode boxes, alive bitmask, global max coord
    float lmax = NEG_INF;
#pragma unroll
    for (int k2 = 0; k2 < 4; k2++) {
        int i = k2 * 1024 + tid;
        unsigned long long e = scand[i];
        unsigned int key = ~(unsigned int)(e >> 32);
        unsigned int idx = (unsigned int)e;
        float sc; float4 bx = make_float4(0.f, 0.f, 0.f, 0.f); int lbl = 0;
        bool alive = (key != 0u);
        if (alive) {
            sc = __uint_as_float(key & 0x7FFFFFFFu);
            int nI = (int)(idx / 80u); lbl = (int)idx - nI * 80;
            int m = (nI < 1083) ? 0 : ((nI < 5415) ? 1 : 2);
            int rem = nI - c_nb[m];
            int locm = rem / 3, a = rem - locm * 3;
            const float* mp = (m == 0) ? m0 : ((m == 1) ? m1 : m2);
            size_t HW = (size_t)c_HW[m];
            const float* bp = mp + ((size_t)b * 255 + a * 85) * HW + locm;
            float tx = bp[0], ty = bp[HW], tw = bp[2 * HW], th = bp[3 * HW];
            float s = c_str[m]; int W = c_W[m];
            int hh = locm / W, ww = locm - hh * W;
            float sx = sigm(tx), sy = sigm(ty);
            float cx = (float)ww * s + 0.5f * s + (sx - 0.5f) * s;
            float cy = (float)hh * s + 0.5f * s + (sy - 0.5f) * s;
            float wx = c_bw2[m * 3 + a] * expf(tw);
            float wy = c_bh2[m * 3 + a] * expf(th);
            bx = make_float4(cx - wx, cy - wy, cx + wx, cy + wy);
        } else sc = NEG_INF;
        sbox[i] = bx; ss[i] = sc; slbl[i] = lbl;
        unsigned int bal = __ballot_sync(0xffffffffu, alive);
        if ((tid & 31) == 0) salive[k2 * 32 + (tid >> 5)] = bal;
        float rm = alive ? fmaxf(fmaxf(bx.x, bx.y), fmaxf(bx.z, bx.w)) : 0.f;
        lmax = fmaxf(lmax, rm);
    }
    for (int o = 16; o; o >>= 1) lmax = fmaxf(lmax, __shfl_xor_sync(0xffffffffu, lmax, o));
    if ((tid & 31) == 0) wred[tid >> 5] = lmax;
    __syncthreads();
    if (tid < 32) {
        float v = wred[tid];
        for (int o = 16; o; o >>= 1) v = fmaxf(v, __shfl_xor_sync(0xffffffffu, v, o));
        if (tid == 0) { smaxc = v; sfrontw = 0; }
    }
    __syncthreads();
    float ob = smaxc + 1.0f;
    for (int i = tid; i < TOPK; i += 1024) soff[i] = (float)slbl[i] * ob;
    __syncthreads();

    // greedy NMS
    for (int it = 0; it < MAXDET; ++it) {
        if (tid < 32) {
            int fw = sfrontw;
            int j = -1;
            while (fw < 128) {
                unsigned int wv = (fw + tid < 128) ? salive[fw + tid] : 0u;
                unsigned int bal = __ballot_sync(0xffffffffu, wv != 0u);
                if (bal) {
                    int wl = __ffs(bal) - 1;
                    unsigned int w2 = __shfl_sync(0xffffffffu, wv, wl);
                    j = (fw + wl) * 32 + (__ffs(w2) - 1);
                    if (tid == 0) sfrontw = fw + wl;
                    break;
                }
                fw += 32;
            }
            if (tid == 0) {
                skeep = (j >= 0) ? 1 : 0;
                sj = (j >= 0) ? j : 0;
                if (j >= 0) {
                    float* o = out + (size_t)(b * MAXDET + it) * 5;
                    float4 bxj = sbox[j];
                    o[0] = bxj.x; o[1] = bxj.y; o[2] = bxj.z; o[3] = bxj.w; o[4] = ss[j];
                    if (out_size > BATCH * MAXDET * 5)
                        out[BATCH * MAXDET * 5 + b * MAXDET + it] = (float)slbl[j];
                }
            }
        }
        __syncthreads();
        if (!skeep) {
            for (int r = it + tid; r < MAXDET; r += 1024) {
                float* o = out + (size_t)(b * MAXDET + r) * 5;
                o[0] = 0.f; o[1] = 0.f; o[2] = 0.f; o[3] = 0.f; o[4] = 0.f;
                if (out_size > BATCH * MAXDET * 5)
                    out[BATCH * MAXDET * 5 + b * MAXDET + r] = -1.0f;
            }
            break;
        }
        int j = sj;
        float oj = soff[j];
        float4 bj = sbox[j];
        float jx0 = bj.x + oj, jy0 = bj.y + oj, jx1 = bj.z + oj, jy1 = bj.w + oj;
        float a1 = (jx1 - jx0) * (jy1 - jy0);
#pragma unroll
        for (int k2 = 0; k2 < 4; k2++) {
            int i = k2 * 1024 + tid;
            float sct = ss[i];
            bool aliveN = (sct != NEG_INF);
            if (aliveN) {
                float ot = soff[i]; float4 bt = sbox[i];
                float tx0 = bt.x + ot, ty0 = bt.y + ot, tx1 = bt.z + ot, ty1 = bt.w + ot;
                float tlx = fmaxf(jx0, tx0), tly = fmaxf(jy0, ty0);
                float brx = fminf(jx1, tx1), bry = fminf(jy1, ty1);
                float iw = fmaxf(brx - tlx, 0.f), ih = fmaxf(bry - tly, 0.f);
                float inter = iw * ih;
                float a2 = (tx1 - tx0) * (ty1 - ty0);
                float iou = inter / (a1 + a2 - inter + 1e-12f);
                if (iou > 0.45f) { ss[i] = NEG_INF; aliveN = false; }
            }
            unsigned int bal = __ballot_sync(0xffffffffu, aliveN);
            if ((tid & 31) == 0) salive[k2 * 32 + (tid >> 5)] = bal;
        }
        __syncthreads();
    }
}

// ---------------- launcher ----------------
extern "C" void kernel_launch(void* const* d_in, const int* in_sizes, int n_in,
                              void* d_out, int out_size) {
    const float* m0 = (const float*)d_in[0];
    const float* m1 = (const float*)d_in[1];
    const float* m2 = (const float*)d_in[2];
    float* out = (float*)d_out;

    cudaFuncSetAttribute(finish_kernel, cudaFuncAttributeMaxDynamicSharedMemorySize, 180224);

    obj_kernel<<<(BATCH * 3 * NLOC + 255) / 256, 256>>>(m0, m1, m2);
    amax_kernel<<<dim3((NLOC + 511) / 512, 3, BATCH), 512>>>(m0, m1, m2);
    thr_kernel<<<BATCH, 1024>>>();
    cand_kernel<<<dim3((NLOC + 511) / 512, 240, BATCH), 512>>>(m0, m1, m2);
    finish_kernel<<<BATCH, 1024, 180224>>>(m0, m1, m2, out, out_size);
}